// round 4
// baseline (speedup 1.0000x reference)
#include <cuda_runtime.h>

#define BATCH 512
#define SEQ   512
#define VOCAB 1000
#define EMB   100
#define UNITS 64

typedef unsigned long long ull;

// Scratch: projected embedding table (emb @ Wxh + b), 1000 x 64 fp32 = 256 KB.
__device__ float g_embproj[VOCAB * UNITS];

// ---- packed f32x2 helpers (Blackwell 2xFP32 path, PTX-only) ----
__device__ __forceinline__ ull fma2(ull a, ull b, ull c) {
    ull d;
    asm("fma.rn.f32x2 %0, %1, %2, %3;" : "=l"(d) : "l"(a), "l"(b), "l"(c));
    return d;
}
__device__ __forceinline__ ull add2(ull a, ull b) {
    ull d;
    asm("add.rn.f32x2 %0, %1, %2;" : "=l"(d) : "l"(a), "l"(b));
    return d;
}
__device__ __forceinline__ ull pack2(float lo, float hi) {
    ull d;
    asm("mov.b64 %0, {%1, %2};"
        : "=l"(d) : "r"(__float_as_uint(lo)), "r"(__float_as_uint(hi)));
    return d;
}
__device__ __forceinline__ void unpack2(ull v, float& lo, float& hi) {
    unsigned a, b;
    asm("mov.b64 {%0, %1}, %2;" : "=r"(a), "=r"(b) : "l"(v));
    lo = __uint_as_float(a);
    hi = __uint_as_float(b);
}

// tanh(x) = 1 - 2*rcp(exp2(2*log2e*x)+1). Saturates correctly at +/-1.
__device__ __forceinline__ float tanh_fast(float x) {
    float e, r;
    asm("ex2.approx.f32 %0, %1;" : "=f"(e) : "f"(x * 2.8853900817779268f));
    asm("rcp.approx.f32 %0, %1;" : "=f"(r) : "f"(e + 1.0f));
    return fmaf(-2.0f, r, 1.0f);
}

// ---------------------------------------------------------------------------
// Prologue: embproj[v][u] = sum_d emb[v][d] * Wxh[d][u] + b[u]
// ---------------------------------------------------------------------------
__global__ void k_embproj(const float* __restrict__ emb,
                          const float* __restrict__ Wxh,
                          const float* __restrict__ bias) {
    int v = blockIdx.x;        // vocab id
    int u = threadIdx.x;       // unit
    const float* er = emb + v * EMB;
    float a0 = bias[u], a1 = 0.f, a2 = 0.f, a3 = 0.f;
#pragma unroll
    for (int d = 0; d < EMB; d += 4) {
        a0 = fmaf(__ldg(er + d),     __ldg(Wxh + (d)     * UNITS + u), a0);
        a1 = fmaf(__ldg(er + d + 1), __ldg(Wxh + (d + 1) * UNITS + u), a1);
        a2 = fmaf(__ldg(er + d + 2), __ldg(Wxh + (d + 2) * UNITS + u), a2);
        a3 = fmaf(__ldg(er + d + 3), __ldg(Wxh + (d + 3) * UNITS + u), a3);
    }
    g_embproj[v * UNITS + u] = (a0 + a1) + (a2 + a3);
}

// ---------------------------------------------------------------------------
// Main: TWO batch rows per warp (independent recurrent chains interleaved for
// ILP — weight registers are shared since they depend only on the lane).
// Lane l owns units u0=2l, u1=2l+1 of both rows.
// 128 blocks x 2 warps x 2 rows = 512 rows.
// ---------------------------------------------------------------------------
__global__ __launch_bounds__(64, 1)
void k_rnn(const int*   __restrict__ tokens,
           const float* __restrict__ Whh,
           const float* __restrict__ Wout,
           const float* __restrict__ bout,
           float*       __restrict__ out) {
    __shared__ __align__(16) float hs[2][2][UNITS];  // [warp][row][unit]
    __shared__ int tok[2][2][SEQ];                   // [warp][row][t]

    const int w    = threadIdx.x >> 5;
    const int lane = threadIdx.x & 31;
    const int rowA = blockIdx.x * 4 + w * 2;
    const int rowB = rowA + 1;

    // Stage both rows' tokens into smem (coalesced int4).
#pragma unroll
    for (int r = 0; r < 2; ++r) {
        const int4* src = (const int4*)(tokens + (rowA + r) * SEQ);
        int4* dst = (int4*)tok[w][r];
#pragma unroll
        for (int i = 0; i < 4; ++i)
            dst[lane + 32 * i] = src[lane + 32 * i];
    }

    // Weight registers, k-pair packed (shared across both rows):
    //   wq0[j] = (W[2j][u0], W[2j+1][u0]),  wq1[j] = (W[2j][u1], W[2j+1][u1])
    ull wq0[UNITS / 2], wq1[UNITS / 2];
#pragma unroll
    for (int j = 0; j < UNITS / 2; ++j) {
        float2 we = *(const float2*)(Whh + (2 * j)     * UNITS + 2 * lane);
        float2 wo = *(const float2*)(Whh + (2 * j + 1) * UNITS + 2 * lane);
        wq0[j] = pack2(we.x, wo.x);
        wq1[j] = pack2(we.y, wo.y);
    }

    // h0 = 0 for both rows.
    *(float2*)(hs[w][0] + 2 * lane) = make_float2(0.f, 0.f);
    *(float2*)(hs[w][1] + 2 * lane) = make_float2(0.f, 0.f);
    __syncwarp();

    const float* ep = g_embproj;
    float* hrowA = hs[w][0];
    float* hrowB = hs[w][1];
    const ull* hpA = (const ull*)hrowA;
    const ull* hpB = (const ull*)hrowB;

    float hA0 = 0.f, hA1 = 0.f, hB0 = 0.f, hB1 = 0.f;

    // Double-buffered gathers, prefetch distance 2, per row.
    float2 xAa = __ldg((const float2*)(ep + tok[w][0][0] * UNITS + 2 * lane));
    float2 xAb = __ldg((const float2*)(ep + tok[w][0][1] * UNITS + 2 * lane));
    float2 xBa = __ldg((const float2*)(ep + tok[w][1][0] * UNITS + 2 * lane));
    float2 xBb = __ldg((const float2*)(ep + tok[w][1][1] * UNITS + 2 * lane));

    // One recurrence step for BOTH rows, interleaved. 4 accums per unit per
    // row (FFMA depth 8, 2-level add2 tree) — ILP comes from the dual rows.
#define STEP2(xA, xB)                                                         \
    {                                                                         \
        ull A0[4], B0[4], A1[4], B1[4];                                       \
        A0[0] = pack2((xA).x, 0.f);  B0[0] = pack2((xA).y, 0.f);              \
        A1[0] = pack2((xB).x, 0.f);  B1[0] = pack2((xB).y, 0.f);              \
        _Pragma("unroll")                                                     \
        for (int i = 1; i < 4; ++i) {                                         \
            A0[i] = 0ull; B0[i] = 0ull; A1[i] = 0ull; B1[i] = 0ull;           \
        }                                                                     \
        _Pragma("unroll")                                                     \
        for (int jj = 0; jj < 16; ++jj) {                                     \
            ulonglong2 qa = *(const ulonglong2*)(hpA + 2 * jj);               \
            ulonglong2 qb = *(const ulonglong2*)(hpB + 2 * jj);               \
            const int i0 = (2 * jj) & 3, i1 = (2 * jj + 1) & 3;               \
            A0[i0] = fma2(qa.x, wq0[2 * jj], A0[i0]);                         \
            B0[i0] = fma2(qa.x, wq1[2 * jj], B0[i0]);                         \
            A1[i0] = fma2(qb.x, wq0[2 * jj], A1[i0]);                         \
            B1[i0] = fma2(qb.x, wq1[2 * jj], B1[i0]);                         \
            A0[i1] = fma2(qa.y, wq0[2 * jj + 1], A0[i1]);                     \
            B0[i1] = fma2(qa.y, wq1[2 * jj + 1], B0[i1]);                     \
            A1[i1] = fma2(qb.y, wq0[2 * jj + 1], A1[i1]);                     \
            B1[i1] = fma2(qb.y, wq1[2 * jj + 1], B1[i1]);                     \
        }                                                                     \
        ull sA0 = add2(add2(A0[0], A0[1]), add2(A0[2], A0[3]));               \
        ull sB0 = add2(add2(B0[0], B0[1]), add2(B0[2], B0[3]));               \
        ull sA1 = add2(add2(A1[0], A1[1]), add2(A1[2], A1[3]));               \
        ull sB1 = add2(add2(B1[0], B1[1]), add2(B1[2], B1[3]));               \
        float p, q;                                                           \
        unpack2(sA0, p, q); hA0 = tanh_fast(p + q);                           \
        unpack2(sB0, p, q); hA1 = tanh_fast(p + q);                           \
        unpack2(sA1, p, q); hB0 = tanh_fast(p + q);                           \
        unpack2(sB1, p, q); hB1 = tanh_fast(p + q);                           \
        *(float2*)(hrowA + 2 * lane) = make_float2(hA0, hA1);                 \
        *(float2*)(hrowB + 2 * lane) = make_float2(hB0, hB1);                 \
        __syncwarp();                                                         \
    }

    for (int t = 0; t < SEQ; t += 2) {
        int i2 = (t + 2 < SEQ) ? t + 2 : SEQ - 1;
        int i3 = (t + 3 < SEQ) ? t + 3 : SEQ - 1;
        float2 nAa = __ldg((const float2*)(ep + tok[w][0][i2] * UNITS + 2 * lane));
        float2 nAb = __ldg((const float2*)(ep + tok[w][0][i3] * UNITS + 2 * lane));
        float2 nBa = __ldg((const float2*)(ep + tok[w][1][i2] * UNITS + 2 * lane));
        float2 nBb = __ldg((const float2*)(ep + tok[w][1][i3] * UNITS + 2 * lane));

        STEP2(xAa, xBa);
        STEP2(xAb, xBb);

        xAa = nAa; xAb = nAb; xBa = nBa; xBb = nBb;
    }
#undef STEP2

    // Epilogue: sigmoid(hT @ Wout + bout) for both rows.
    float2 wo = *(const float2*)(Wout + 2 * lane);
    float pA = hA0 * wo.x + hA1 * wo.y;
    float pB = hB0 * wo.x + hB1 * wo.y;
#pragma unroll
    for (int o = 16; o; o >>= 1) {
        pA += __shfl_xor_sync(0xffffffffu, pA, o);
        pB += __shfl_xor_sync(0xffffffffu, pB, o);
    }
    if (lane == 0) {
        float bo = bout[0];
        float e, r;
        asm("ex2.approx.f32 %0, %1;" : "=f"(e) : "f"(-(pA + bo) * 1.4426950408889634f));
        asm("rcp.approx.f32 %0, %1;" : "=f"(r) : "f"(1.0f + e));
        out[rowA] = r;
        asm("ex2.approx.f32 %0, %1;" : "=f"(e) : "f"(-(pB + bo) * 1.4426950408889634f));
        asm("rcp.approx.f32 %0, %1;" : "=f"(r) : "f"(1.0f + e));
        out[rowB] = r;
    }
}

extern "C" void kernel_launch(void* const* d_in, const int* in_sizes, int n_in,
                              void* d_out, int out_size) {
    const int*   tokens = (const int*)d_in[0];
    const float* emb    = (const float*)d_in[1];
    const float* Wxh    = (const float*)d_in[2];
    const float* Whh    = (const float*)d_in[3];
    const float* b      = (const float*)d_in[4];
    const float* Wout   = (const float*)d_in[5];
    const float* bout   = (const float*)d_in[6];
    float* out = (float*)d_out;

    k_embproj<<<VOCAB, UNITS>>>(emb, Wxh, b);
    k_rnn<<<BATCH / 4, 64>>>(tokens, Whh, Wout, bout, out);
}

// round 5
// speedup vs baseline: 1.3593x; 1.3593x over previous
#include <cuda_runtime.h>

#define BATCH 512
#define SEQ   512
#define VOCAB 1000
#define EMB   100
#define UNITS 64

typedef unsigned long long ull;

// Scratch: projected embedding table (emb @ Wxh + b), 1000 x 64 fp32 = 256 KB.
__device__ float g_embproj[VOCAB * UNITS];

// ---- packed f32x2 helpers (Blackwell 2xFP32 path, PTX-only) ----
__device__ __forceinline__ ull fma2(ull a, ull b, ull c) {
    ull d;
    asm("fma.rn.f32x2 %0, %1, %2, %3;" : "=l"(d) : "l"(a), "l"(b), "l"(c));
    return d;
}
__device__ __forceinline__ ull add2(ull a, ull b) {
    ull d;
    asm("add.rn.f32x2 %0, %1, %2;" : "=l"(d) : "l"(a), "l"(b));
    return d;
}
__device__ __forceinline__ ull pack2(float lo, float hi) {
    ull d;
    asm("mov.b64 %0, {%1, %2};"
        : "=l"(d) : "r"(__float_as_uint(lo)), "r"(__float_as_uint(hi)));
    return d;
}
__device__ __forceinline__ void unpack2(ull v, float& lo, float& hi) {
    unsigned a, b;
    asm("mov.b64 {%0, %1}, %2;" : "=r"(a), "=r"(b) : "l"(v));
    lo = __uint_as_float(a);
    hi = __uint_as_float(b);
}

// tanh(x) = 1 - 2*rcp(exp2(2*log2e*x)+1). Saturates correctly at +/-1.
__device__ __forceinline__ float tanh_fast(float x) {
    float e, r;
    asm("ex2.approx.f32 %0, %1;" : "=f"(e) : "f"(x * 2.8853900817779268f));
    asm("rcp.approx.f32 %0, %1;" : "=f"(r) : "f"(e + 1.0f));
    return fmaf(-2.0f, r, 1.0f);
}

// ---------------------------------------------------------------------------
// Prologue: embproj[v][u] = sum_d emb[v][d] * Wxh[d][u] + b[u]
// ---------------------------------------------------------------------------
__global__ void k_embproj(const float* __restrict__ emb,
                          const float* __restrict__ Wxh,
                          const float* __restrict__ bias) {
    int v = blockIdx.x;        // vocab id
    int u = threadIdx.x;       // unit
    const float* er = emb + v * EMB;
    float a0 = bias[u], a1 = 0.f, a2 = 0.f, a3 = 0.f;
#pragma unroll
    for (int d = 0; d < EMB; d += 4) {
        a0 = fmaf(__ldg(er + d),     __ldg(Wxh + (d)     * UNITS + u), a0);
        a1 = fmaf(__ldg(er + d + 1), __ldg(Wxh + (d + 1) * UNITS + u), a1);
        a2 = fmaf(__ldg(er + d + 2), __ldg(Wxh + (d + 2) * UNITS + u), a2);
        a3 = fmaf(__ldg(er + d + 3), __ldg(Wxh + (d + 3) * UNITS + u), a3);
    }
    g_embproj[v * UNITS + u] = (a0 + a1) + (a2 + a3);
}

// ---------------------------------------------------------------------------
// Main: each batch row handled by a WARP PAIR (warps 2r, 2r+1 of the block).
// Lane owns ONE unit u = (w&1)*32 + lane. 128 blocks x 8 warps = 1024 warps
// -> exactly 2 warps per SMSP on 128 SMs; the two co-resident warps belong to
// DIFFERENT rows, so their dependency chains overlap.
// h is exchanged via a ping-pong smem buffer with one named barrier per step.
// ---------------------------------------------------------------------------
__global__ __launch_bounds__(256, 1)
void k_rnn(const int*   __restrict__ tokens,
           const float* __restrict__ Whh,
           const float* __restrict__ Wout,
           const float* __restrict__ bout,
           float*       __restrict__ out) {
    __shared__ __align__(16) float hs[4][2][UNITS];  // [row][pingpong][unit]
    __shared__ int tok[4][SEQ];                      // token*64, premultiplied
    __shared__ float ps[4][2];                       // epilogue partials

    const int w    = threadIdx.x >> 5;
    const int lane = threadIdx.x & 31;
    const int r    = w >> 1;            // row-in-block 0..3
    const int p    = w & 1;             // half: units [32p, 32p+32)
    const int u    = p * 32 + lane;     // this lane's unit
    const int row  = blockIdx.x * 4 + r;
    const int bid  = r + 1;             // named barrier id for this row

    // Stage this row's tokens (premultiplied by UNITS), warp pair splits it.
    {
        const int4* src = (const int4*)(tokens + row * SEQ + p * 256);
        int4* dst = (int4*)(tok[r] + p * 256);
#pragma unroll
        for (int i = 0; i < 2; ++i) {
            int4 v = src[lane + 32 * i];
            v.x *= UNITS; v.y *= UNITS; v.z *= UNITS; v.w *= UNITS;
            dst[lane + 32 * i] = v;
        }
    }

    // Weights: this lane's column u of Whh, k-pair packed.
    //   wq[j] = (Whh[2j][u], Whh[2j+1][u])
    ull wq[UNITS / 2];
#pragma unroll
    for (int j = 0; j < UNITS / 2; ++j)
        wq[j] = pack2(Whh[(2 * j) * UNITS + u], Whh[(2 * j + 1) * UNITS + u]);

    // h0 = 0 in buffer 0.
    hs[r][0][u] = 0.f;
    __syncthreads();

    const float* ep = g_embproj;
    float* buf0 = hs[r][0];
    float* buf1 = hs[r][1];

    float hv = 0.f;

    // Double-buffered gathers, prefetch distance 2 (one float per lane).
    float xa = __ldg(ep + tok[r][0] + u);
    float xb = __ldg(ep + tok[r][1] + u);

    // One recurrence step: read h from rbuf, write new h to wbuf, barrier.
    // acc pairs hold (sum over even k, sum over odd k); 4 accums -> depth 8.
#define STEP(xcur, rbuf, wbuf)                                                \
    {                                                                         \
        const ull* hp = (const ull*)(rbuf);                                   \
        ull a0 = pack2((xcur), 0.f), a1 = 0ull, a2 = 0ull, a3 = 0ull;         \
        _Pragma("unroll")                                                     \
        for (int g = 0; g < 8; ++g) {                                         \
            ulonglong2 q01 = *(const ulonglong2*)(hp + 4 * g);                \
            ulonglong2 q23 = *(const ulonglong2*)(hp + 4 * g + 2);            \
            a0 = fma2(q01.x, wq[4 * g],     a0);                              \
            a1 = fma2(q01.y, wq[4 * g + 1], a1);                              \
            a2 = fma2(q23.x, wq[4 * g + 2], a2);                              \
            a3 = fma2(q23.y, wq[4 * g + 3], a3);                              \
        }                                                                     \
        ull s = add2(add2(a0, a1), add2(a2, a3));                             \
        float se, so;                                                         \
        unpack2(s, se, so);                                                   \
        hv = tanh_fast(se + so);                                              \
        (wbuf)[u] = hv;                                                       \
        asm volatile("bar.sync %0, 64;" :: "r"(bid) : "memory");              \
    }

    for (int t = 0; t < SEQ; t += 2) {
        int i2 = (t + 2 < SEQ) ? t + 2 : SEQ - 1;
        int i3 = (t + 3 < SEQ) ? t + 3 : SEQ - 1;
        float xn0 = __ldg(ep + tok[r][i2] + u);
        float xn1 = __ldg(ep + tok[r][i3] + u);

        STEP(xa, buf0, buf1);
        STEP(xb, buf1, buf0);

        xa = xn0;
        xb = xn1;
    }
#undef STEP

    // Epilogue: sigmoid(hT @ Wout + bout). Each warp reduces its 32 units,
    // pair combines via smem + named barrier.
    float part = hv * Wout[u];
#pragma unroll
    for (int o = 16; o; o >>= 1)
        part += __shfl_xor_sync(0xffffffffu, part, o);
    if (lane == 0) ps[r][p] = part;
    asm volatile("bar.sync %0, 64;" :: "r"(bid) : "memory");
    if (p == 0 && lane == 0) {
        float z = ps[r][0] + ps[r][1] + bout[0];
        float e, rc;
        asm("ex2.approx.f32 %0, %1;" : "=f"(e) : "f"(-z * 1.4426950408889634f));
        asm("rcp.approx.f32 %0, %1;" : "=f"(rc) : "f"(1.0f + e));
        out[row] = rc;
    }
}

extern "C" void kernel_launch(void* const* d_in, const int* in_sizes, int n_in,
                              void* d_out, int out_size) {
    const int*   tokens = (const int*)d_in[0];
    const float* emb    = (const float*)d_in[1];
    const float* Wxh    = (const float*)d_in[2];
    const float* Whh    = (const float*)d_in[3];
    const float* b      = (const float*)d_in[4];
    const float* Wout   = (const float*)d_in[5];
    const float* bout   = (const float*)d_in[6];
    float* out = (float*)d_out;

    k_embproj<<<VOCAB, UNITS>>>(emb, Wxh, b);
    k_rnn<<<BATCH / 4, 256>>>(tokens, Whh, Wout, bout, out);
}

// round 6
// speedup vs baseline: 1.7845x; 1.3128x over previous
#include <cuda_runtime.h>

#define BATCH 512
#define SEQ   512
#define VOCAB 1000
#define EMB   100
#define UNITS 64

typedef unsigned long long ull;

// Scratch: projected embedding table (emb @ Wxh + b), 1000 x 64 fp32 = 256 KB.
__device__ float g_embproj[VOCAB * UNITS];

// ---- packed f32x2 helpers (Blackwell 2xFP32 path, PTX-only) ----
__device__ __forceinline__ ull fma2(ull a, ull b, ull c) {
    ull d;
    asm("fma.rn.f32x2 %0, %1, %2, %3;" : "=l"(d) : "l"(a), "l"(b), "l"(c));
    return d;
}
__device__ __forceinline__ ull add2(ull a, ull b) {
    ull d;
    asm("add.rn.f32x2 %0, %1, %2;" : "=l"(d) : "l"(a), "l"(b));
    return d;
}
__device__ __forceinline__ ull pack2(float lo, float hi) {
    ull d;
    asm("mov.b64 %0, {%1, %2};"
        : "=l"(d) : "r"(__float_as_uint(lo)), "r"(__float_as_uint(hi)));
    return d;
}
__device__ __forceinline__ void unpack2(ull v, float& lo, float& hi) {
    unsigned a, b;
    asm("mov.b64 {%0, %1}, %2;" : "=r"(a), "=r"(b) : "l"(v));
    lo = __uint_as_float(a);
    hi = __uint_as_float(b);
}

// Single-MUFU tanh (sm_75+). 16-cyc chain vs 44 for the ex2/rcp version.
__device__ __forceinline__ float tanh_mufu(float x) {
    float y;
    asm("tanh.approx.f32 %0, %1;" : "=f"(y) : "f"(x));
    return y;
}

// ---------------------------------------------------------------------------
// Prologue: embproj[v][u] = sum_d emb[v][d] * Wxh[d][u] + b[u]
// ---------------------------------------------------------------------------
__global__ void k_embproj(const float* __restrict__ emb,
                          const float* __restrict__ Wxh,
                          const float* __restrict__ bias) {
    int v = blockIdx.x;        // vocab id
    int u = threadIdx.x;       // unit
    const float* er = emb + v * EMB;
    float a0 = bias[u], a1 = 0.f, a2 = 0.f, a3 = 0.f;
#pragma unroll
    for (int d = 0; d < EMB; d += 4) {
        a0 = fmaf(__ldg(er + d),     __ldg(Wxh + (d)     * UNITS + u), a0);
        a1 = fmaf(__ldg(er + d + 1), __ldg(Wxh + (d + 1) * UNITS + u), a1);
        a2 = fmaf(__ldg(er + d + 2), __ldg(Wxh + (d + 2) * UNITS + u), a2);
        a3 = fmaf(__ldg(er + d + 3), __ldg(Wxh + (d + 3) * UNITS + u), a3);
    }
    g_embproj[v * UNITS + u] = (a0 + a1) + (a2 + a3);
}

// ---------------------------------------------------------------------------
// Main: one warp per batch row (R3 structure). Lane l owns units 2l, 2l+1.
// k-pair packed FFMA2 matvec (64 FFMA2 + 8 LDS.128 per step).
// Latency trims: MUFU tanh, no per-step syncwarp (compiler barrier only;
// smem LSU is in-order within a convergent warp), premultiplied+padded
// token offsets, prefetch distance 2.
// ---------------------------------------------------------------------------
__global__ __launch_bounds__(128, 1)
void k_rnn(const int*   __restrict__ tokens,
           const float* __restrict__ Whh,
           const float* __restrict__ Wout,
           const float* __restrict__ bout,
           float*       __restrict__ out) {
    __shared__ __align__(16) float hs[4][UNITS];   // h per warp
    __shared__ int tok[4][SEQ + 4];                // token*UNITS, padded

    const int w    = threadIdx.x >> 5;
    const int lane = threadIdx.x & 31;
    const int row  = blockIdx.x * 4 + w;

    // Stage tokens premultiplied by UNITS (coalesced int4), pad 2 entries.
    {
        const int4* src = (const int4*)(tokens + row * SEQ);
        int4* dst = (int4*)tok[w];
#pragma unroll
        for (int i = 0; i < 4; ++i) {
            int4 v = src[lane + 32 * i];
            v.x *= UNITS; v.y *= UNITS; v.z *= UNITS; v.w *= UNITS;
            dst[lane + 32 * i] = v;
        }
        if (lane == 0) {
            int last = tok[w][SEQ - 1];
            tok[w][SEQ]     = last;
            tok[w][SEQ + 1] = last;
        }
    }

    // Weight registers, k-pair packed:
    //   wq0[j] = (W[2j][u0], W[2j+1][u0]),  wq1[j] = (W[2j][u1], W[2j+1][u1])
    ull wq0[UNITS / 2], wq1[UNITS / 2];
#pragma unroll
    for (int j = 0; j < UNITS / 2; ++j) {
        float2 we = *(const float2*)(Whh + (2 * j)     * UNITS + 2 * lane);
        float2 wo = *(const float2*)(Whh + (2 * j + 1) * UNITS + 2 * lane);
        wq0[j] = pack2(we.x, wo.x);
        wq1[j] = pack2(we.y, wo.y);
    }

    // h0 = 0
    *(float2*)(hs[w] + 2 * lane) = make_float2(0.f, 0.f);
    __syncwarp();

    const float* epl = g_embproj + 2 * lane;   // lane-fixed base
    float* hrow = hs[w];
    const ull* hp = (const ull*)hrow;          // packed (h_2j, h_2j+1) pairs

    float h0v = 0.0f, h1v = 0.0f;

    // Double-buffered gather, prefetch distance 2.
    float2 xa = __ldg((const float2*)(epl + tok[w][0]));
    float2 xb = __ldg((const float2*)(epl + tok[w][1]));

    // One recurrence step. 8 accumulators per unit (FFMA depth 4), 3-level
    // add2 tree, MUFU tanh, STS publish, compiler-only memory barrier.
#define RNN_BODY(xcur)                                                        \
    {                                                                         \
        ull A[8], B[8];                                                       \
        A[0] = pack2((xcur).x, 0.f);                                          \
        B[0] = pack2((xcur).y, 0.f);                                          \
        _Pragma("unroll")                                                     \
        for (int i = 1; i < 8; ++i) { A[i] = 0ull; B[i] = 0ull; }             \
        _Pragma("unroll")                                                     \
        for (int g = 0; g < 4; ++g) {                                         \
            ulonglong2 q0 = *(const ulonglong2*)(hp + 8 * g);                 \
            ulonglong2 q1 = *(const ulonglong2*)(hp + 8 * g + 2);             \
            ulonglong2 q2 = *(const ulonglong2*)(hp + 8 * g + 4);             \
            ulonglong2 q3 = *(const ulonglong2*)(hp + 8 * g + 6);             \
            A[0] = fma2(q0.x, wq0[8 * g + 0], A[0]);                          \
            B[0] = fma2(q0.x, wq1[8 * g + 0], B[0]);                          \
            A[1] = fma2(q0.y, wq0[8 * g + 1], A[1]);                          \
            B[1] = fma2(q0.y, wq1[8 * g + 1], B[1]);                          \
            A[2] = fma2(q1.x, wq0[8 * g + 2], A[2]);                          \
            B[2] = fma2(q1.x, wq1[8 * g + 2], B[2]);                          \
            A[3] = fma2(q1.y, wq0[8 * g + 3], A[3]);                          \
            B[3] = fma2(q1.y, wq1[8 * g + 3], B[3]);                          \
            A[4] = fma2(q2.x, wq0[8 * g + 4], A[4]);                          \
            B[4] = fma2(q2.x, wq1[8 * g + 4], B[4]);                          \
            A[5] = fma2(q2.y, wq0[8 * g + 5], A[5]);                          \
            B[5] = fma2(q2.y, wq1[8 * g + 5], B[5]);                          \
            A[6] = fma2(q3.x, wq0[8 * g + 6], A[6]);                          \
            B[6] = fma2(q3.x, wq1[8 * g + 6], B[6]);                          \
            A[7] = fma2(q3.y, wq0[8 * g + 7], A[7]);                          \
            B[7] = fma2(q3.y, wq1[8 * g + 7], B[7]);                          \
        }                                                                     \
        ull sa = add2(add2(add2(A[0], A[1]), add2(A[2], A[3])),               \
                      add2(add2(A[4], A[5]), add2(A[6], A[7])));              \
        ull sb = add2(add2(add2(B[0], B[1]), add2(B[2], B[3])),               \
                      add2(add2(B[4], B[5]), add2(B[6], B[7])));              \
        float sa0, sa1, sb0, sb1;                                             \
        unpack2(sa, sa0, sa1);                                                \
        unpack2(sb, sb0, sb1);                                                \
        h0v = tanh_mufu(sa0 + sa1);                                           \
        h1v = tanh_mufu(sb0 + sb1);                                           \
        *(float2*)(hrow + 2 * lane) = make_float2(h0v, h1v);                  \
        asm volatile("" ::: "memory");                                        \
    }

    for (int t = 0; t < SEQ; t += 2) {
        float2 xn0 = __ldg((const float2*)(epl + tok[w][t + 2]));
        float2 xn1 = __ldg((const float2*)(epl + tok[w][t + 3]));

        RNN_BODY(xa);
        RNN_BODY(xb);

        xa = xn0;
        xb = xn1;
    }
#undef RNN_BODY

    // Epilogue: sigmoid(hT @ Wout + bout)
    float2 wo = *(const float2*)(Wout + 2 * lane);
    float part = h0v * wo.x + h1v * wo.y;
#pragma unroll
    for (int o = 16; o; o >>= 1)
        part += __shfl_xor_sync(0xffffffffu, part, o);
    if (lane == 0) {
        float z = part + bout[0];
        float e, r;
        asm("ex2.approx.f32 %0, %1;" : "=f"(e) : "f"(-z * 1.4426950408889634f));
        asm("rcp.approx.f32 %0, %1;" : "=f"(r) : "f"(1.0f + e));
        out[row] = r;
    }
}

extern "C" void kernel_launch(void* const* d_in, const int* in_sizes, int n_in,
                              void* d_out, int out_size) {
    const int*   tokens = (const int*)d_in[0];
    const float* emb    = (const float*)d_in[1];
    const float* Wxh    = (const float*)d_in[2];
    const float* Whh    = (const float*)d_in[3];
    const float* b      = (const float*)d_in[4];
    const float* Wout   = (const float*)d_in[5];
    const float* bout   = (const float*)d_in[6];
    float* out = (float*)d_out;

    k_embproj<<<VOCAB, UNITS>>>(emb, Wxh, b);
    k_rnn<<<BATCH / 4, 128>>>(tokens, Whh, Wout, bout, out);
}

// round 7
// speedup vs baseline: 1.8753x; 1.0509x over previous
#include <cuda_runtime.h>

#define BATCH 512
#define SEQ   512
#define VOCAB 1000
#define EMB   100
#define UNITS 64

typedef unsigned long long ull;

// Scratch: projected embedding table (emb @ Wxh + b), 1000 x 64 fp32 = 256 KB.
__device__ float g_embproj[VOCAB * UNITS];

// ---- packed f32x2 helpers (Blackwell 2xFP32 path, PTX-only) ----
__device__ __forceinline__ ull fma2(ull a, ull b, ull c) {
    ull d;
    asm("fma.rn.f32x2 %0, %1, %2, %3;" : "=l"(d) : "l"(a), "l"(b), "l"(c));
    return d;
}
__device__ __forceinline__ ull mul2(ull a, ull b) {
    ull d;
    asm("mul.rn.f32x2 %0, %1, %2;" : "=l"(d) : "l"(a), "l"(b));
    return d;
}
__device__ __forceinline__ ull add2(ull a, ull b) {
    ull d;
    asm("add.rn.f32x2 %0, %1, %2;" : "=l"(d) : "l"(a), "l"(b));
    return d;
}
__device__ __forceinline__ ull pack2(float lo, float hi) {
    ull d;
    asm("mov.b64 %0, {%1, %2};"
        : "=l"(d) : "r"(__float_as_uint(lo)), "r"(__float_as_uint(hi)));
    return d;
}
__device__ __forceinline__ void unpack2(ull v, float& lo, float& hi) {
    unsigned a, b;
    asm("mov.b64 {%0, %1}, %2;" : "=r"(a), "=r"(b) : "l"(v));
    lo = __uint_as_float(a);
    hi = __uint_as_float(b);
}

// Single-MUFU tanh (sm_75+).
__device__ __forceinline__ float tanh_mufu(float x) {
    float y;
    asm("tanh.approx.f32 %0, %1;" : "=f"(y) : "f"(x));
    return y;
}

// ---------------------------------------------------------------------------
// Prologue: embproj[v][u] = sum_d emb[v][d] * Wxh[d][u] + b[u]
// 256-thread blocks, 4 vocab rows per block.
// ---------------------------------------------------------------------------
__global__ __launch_bounds__(256)
void k_embproj(const float* __restrict__ emb,
               const float* __restrict__ Wxh,
               const float* __restrict__ bias) {
    int v = blockIdx.x * 4 + (threadIdx.x >> 6);
    int u = threadIdx.x & 63;
    if (v >= VOCAB) return;
    const float* er = emb + v * EMB;
    float a0 = bias[u], a1 = 0.f, a2 = 0.f, a3 = 0.f;
#pragma unroll
    for (int d = 0; d < EMB; d += 4) {
        a0 = fmaf(__ldg(er + d),     __ldg(Wxh + (d)     * UNITS + u), a0);
        a1 = fmaf(__ldg(er + d + 1), __ldg(Wxh + (d + 1) * UNITS + u), a1);
        a2 = fmaf(__ldg(er + d + 2), __ldg(Wxh + (d + 2) * UNITS + u), a2);
        a3 = fmaf(__ldg(er + d + 3), __ldg(Wxh + (d + 3) * UNITS + u), a3);
    }
    g_embproj[v * UNITS + u] = (a0 + a1) + (a2 + a3);
}

// ---------------------------------------------------------------------------
// Main: one warp per batch row. Lane l owns units 2l, 2l+1.
// k-pair packed matvec: first K-group initializes the 16 accumulators via
// mul.f32x2 (kills the per-step zero-MOVs); A[0]/B[0] seed from packed x.
// 64 FFMA2-class ops + 8 LDS.128 + 14 ADD2 + 2 MUFU per step.
// ---------------------------------------------------------------------------
__global__ __launch_bounds__(128, 1)
void k_rnn(const int*   __restrict__ tokens,
           const float* __restrict__ Whh,
           const float* __restrict__ Wout,
           const float* __restrict__ bout,
           float*       __restrict__ out) {
    __shared__ __align__(16) float hs[4][UNITS];   // h per warp
    __shared__ __align__(8) int tok[4][SEQ + 4];   // token*UNITS, padded

    const int w    = threadIdx.x >> 5;
    const int lane = threadIdx.x & 31;
    const int row  = blockIdx.x * 4 + w;

    // Stage tokens premultiplied by UNITS (coalesced int4), pad 2 entries.
    {
        const int4* src = (const int4*)(tokens + row * SEQ);
        int4* dst = (int4*)tok[w];
#pragma unroll
        for (int i = 0; i < 4; ++i) {
            int4 v = src[lane + 32 * i];
            v.x *= UNITS; v.y *= UNITS; v.z *= UNITS; v.w *= UNITS;
            dst[lane + 32 * i] = v;
        }
        if (lane == 0) {
            int last = tok[w][SEQ - 1];
            tok[w][SEQ]     = last;
            tok[w][SEQ + 1] = last;
        }
    }

    // Weight registers, k-pair packed:
    //   wq0[j] = (W[2j][u0], W[2j+1][u0]),  wq1[j] = (W[2j][u1], W[2j+1][u1])
    ull wq0[UNITS / 2], wq1[UNITS / 2];
#pragma unroll
    for (int j = 0; j < UNITS / 2; ++j) {
        float2 we = *(const float2*)(Whh + (2 * j)     * UNITS + 2 * lane);
        float2 wo = *(const float2*)(Whh + (2 * j + 1) * UNITS + 2 * lane);
        wq0[j] = pack2(we.x, wo.x);
        wq1[j] = pack2(we.y, wo.y);
    }

    // h0 = 0
    *(float2*)(hs[w] + 2 * lane) = make_float2(0.f, 0.f);
    __syncwarp();

    const float* epl = g_embproj + 2 * lane;   // lane-fixed base
    float* hrow = hs[w];
    const ull* hp = (const ull*)hrow;          // packed (h_2j, h_2j+1) pairs

    float h0v = 0.0f, h1v = 0.0f;

    // Double-buffered gather, prefetch distance 2.
    float2 xa = __ldg((const float2*)(epl + tok[w][0]));
    float2 xb = __ldg((const float2*)(epl + tok[w][1]));

    // One recurrence step. Group 0 initializes accumulators (mul2 / x-seeded
    // fma2); groups 1..3 accumulate. 3-level add2 tree, MUFU tanh.
#define RNN_BODY(xcur)                                                        \
    {                                                                         \
        ull A[8], B[8];                                                       \
        {                                                                     \
            ulonglong2 q0 = *(const ulonglong2*)(hp);                         \
            ulonglong2 q1 = *(const ulonglong2*)(hp + 2);                     \
            ulonglong2 q2 = *(const ulonglong2*)(hp + 4);                     \
            ulonglong2 q3 = *(const ulonglong2*)(hp + 6);                     \
            A[0] = fma2(q0.x, wq0[0], pack2((xcur).x, 0.f));                  \
            B[0] = fma2(q0.x, wq1[0], pack2((xcur).y, 0.f));                  \
            A[1] = mul2(q0.y, wq0[1]);  B[1] = mul2(q0.y, wq1[1]);            \
            A[2] = mul2(q1.x, wq0[2]);  B[2] = mul2(q1.x, wq1[2]);            \
            A[3] = mul2(q1.y, wq0[3]);  B[3] = mul2(q1.y, wq1[3]);            \
            A[4] = mul2(q2.x, wq0[4]);  B[4] = mul2(q2.x, wq1[4]);            \
            A[5] = mul2(q2.y, wq0[5]);  B[5] = mul2(q2.y, wq1[5]);            \
            A[6] = mul2(q3.x, wq0[6]);  B[6] = mul2(q3.x, wq1[6]);            \
            A[7] = mul2(q3.y, wq0[7]);  B[7] = mul2(q3.y, wq1[7]);            \
        }                                                                     \
        _Pragma("unroll")                                                     \
        for (int g = 1; g < 4; ++g) {                                         \
            ulonglong2 q0 = *(const ulonglong2*)(hp + 8 * g);                 \
            ulonglong2 q1 = *(const ulonglong2*)(hp + 8 * g + 2);             \
            ulonglong2 q2 = *(const ulonglong2*)(hp + 8 * g + 4);             \
            ulonglong2 q3 = *(const ulonglong2*)(hp + 8 * g + 6);             \
            A[0] = fma2(q0.x, wq0[8 * g + 0], A[0]);                          \
            B[0] = fma2(q0.x, wq1[8 * g + 0], B[0]);                          \
            A[1] = fma2(q0.y, wq0[8 * g + 1], A[1]);                          \
            B[1] = fma2(q0.y, wq1[8 * g + 1], B[1]);                          \
            A[2] = fma2(q1.x, wq0[8 * g + 2], A[2]);                          \
            B[2] = fma2(q1.x, wq1[8 * g + 2], B[2]);                          \
            A[3] = fma2(q1.y, wq0[8 * g + 3], A[3]);                          \
            B[3] = fma2(q1.y, wq1[8 * g + 3], B[3]);                          \
            A[4] = fma2(q2.x, wq0[8 * g + 4], A[4]);                          \
            B[4] = fma2(q2.x, wq1[8 * g + 4], B[4]);                          \
            A[5] = fma2(q2.y, wq0[8 * g + 5], A[5]);                          \
            B[5] = fma2(q2.y, wq1[8 * g + 5], B[5]);                          \
            A[6] = fma2(q3.x, wq0[8 * g + 6], A[6]);                          \
            B[6] = fma2(q3.x, wq1[8 * g + 6], B[6]);                          \
            A[7] = fma2(q3.y, wq0[8 * g + 7], A[7]);                          \
            B[7] = fma2(q3.y, wq1[8 * g + 7], B[7]);                          \
        }                                                                     \
        ull sa = add2(add2(add2(A[0], A[1]), add2(A[2], A[3])),               \
                      add2(add2(A[4], A[5]), add2(A[6], A[7])));              \
        ull sb = add2(add2(add2(B[0], B[1]), add2(B[2], B[3])),               \
                      add2(add2(B[4], B[5]), add2(B[6], B[7])));              \
        float sa0, sa1, sb0, sb1;                                             \
        unpack2(sa, sa0, sa1);                                                \
        unpack2(sb, sb0, sb1);                                                \
        h0v = tanh_mufu(sa0 + sa1);                                           \
        h1v = tanh_mufu(sb0 + sb1);                                           \
        *(float2*)(hrow + 2 * lane) = make_float2(h0v, h1v);                  \
        asm volatile("" ::: "memory");                                        \
    }

    for (int t = 0; t < SEQ; t += 2) {
        int2 tp = *(const int2*)(tok[w] + t + 2);   // tokens t+2, t+3
        float2 xn0 = __ldg((const float2*)(epl + tp.x));
        float2 xn1 = __ldg((const float2*)(epl + tp.y));

        RNN_BODY(xa);
        RNN_BODY(xb);

        xa = xn0;
        xb = xn1;
    }
#undef RNN_BODY

    // Epilogue: sigmoid(hT @ Wout + bout)
    float2 wo = *(const float2*)(Wout + 2 * lane);
    float part = h0v * wo.x + h1v * wo.y;
#pragma unroll
    for (int o = 16; o; o >>= 1)
        part += __shfl_xor_sync(0xffffffffu, part, o);
    if (lane == 0) {
        float z = part + bout[0];
        float e, r;
        asm("ex2.approx.f32 %0, %1;" : "=f"(e) : "f"(-z * 1.4426950408889634f));
        asm("rcp.approx.f32 %0, %1;" : "=f"(r) : "f"(1.0f + e));
        out[row] = r;
    }
}

extern "C" void kernel_launch(void* const* d_in, const int* in_sizes, int n_in,
                              void* d_out, int out_size) {
    const int*   tokens = (const int*)d_in[0];
    const float* emb    = (const float*)d_in[1];
    const float* Wxh    = (const float*)d_in[2];
    const float* Whh    = (const float*)d_in[3];
    const float* b      = (const float*)d_in[4];
    const float* Wout   = (const float*)d_in[5];
    const float* bout   = (const float*)d_in[6];
    float* out = (float*)d_out;

    k_embproj<<<(VOCAB + 3) / 4, 256>>>(emb, Wxh, b);
    k_rnn<<<BATCH / 4, 128>>>(tokens, Whh, Wout, bout, out);
}